// round 17
// baseline (speedup 1.0000x reference)
#include <cuda_runtime.h>

#define C16  16
#define GH32 32
#define W512 512
#define HW   (512 * 512)

// Constant bank — pure transposes, NO matrix folds (the unfolded concat form
// hidden = relu(W1@x + WB@agg + g1b) replaces W2@s, so prep does no GEMM).
#define OFF_W1 0        // [c][j]  16*32   (= g1w[j][c], first half)
#define OFF_WB 512      // [k][j]  16*32   (= g1w[j][16+k], second half)
#define OFF_G2 1024     // [gp][j][e] 8*32*2 (= g2w[2gp+e][j])
#define OFF_MW 1536     // [c][d]  16*16   (= 0.125 * mw[d][c])
#define OFF_B1 1792     // 32             (g1b raw)
#define OFF_GB 1824     // 16             (g2b)
#define OFF_MB 1840     // 16             (mb)
#define NWC    1856

__constant__ __align__(16) float cwts[NWC];
__device__   __align__(16) float g_wbuf[NWC];
// 64 MB scratch for agg = mw @ s + mb (the sanctioned __device__-global path).
__device__ float g_agg[4 * C16 * HW];

// Packed f32x2 ops (Blackwell sm_103a).
__device__ __forceinline__ float2 ffma2(float2 a, float2 b, float2 c) {
    float2 d;
    asm("fma.rn.f32x2 %0, %1, %2, %3;"
        : "=l"(reinterpret_cast<unsigned long long&>(d))
        : "l"(reinterpret_cast<unsigned long long&>(a)),
          "l"(reinterpret_cast<unsigned long long&>(b)),
          "l"(reinterpret_cast<unsigned long long&>(c)));
    return d;
}
__device__ __forceinline__ float2 fadd2(float2 a, float2 b) {
    float2 d;
    asm("add.rn.f32x2 %0, %1, %2;"
        : "=l"(reinterpret_cast<unsigned long long&>(d))
        : "l"(reinterpret_cast<unsigned long long&>(a)),
          "l"(reinterpret_cast<unsigned long long&>(b)));
    return d;
}
__device__ __forceinline__ float2 dup2(float v) { return make_float2(v, v); }
__device__ __forceinline__ float4 ldc4(int idx) {
    return *reinterpret_cast<const float4*>(&cwts[idx]);
}
__device__ __forceinline__ float2 ldc2(int idx) {
    return *reinterpret_cast<const float2*>(&cwts[idx]);
}

// ---- prep: transpose weights into constant staging buffer (no folds) ----
__global__ void prep_weights(const float* __restrict__ mw,  const float* __restrict__ mb,
                             const float* __restrict__ g1w, const float* __restrict__ g1b,
                             const float* __restrict__ g2w, const float* __restrict__ g2b)
{
    const int t = threadIdx.x;
    for (int i = t; i < C16 * GH32; i += 256) {
        int c = i >> 5, j = i & 31;
        g_wbuf[OFF_W1 + i] = g1w[j * (2 * C16) + c];          // first half
        g_wbuf[OFF_WB + i] = g1w[j * (2 * C16) + C16 + c];    // second half (k=c)
    }
    for (int i = t; i < 8 * GH32 * 2; i += 256) {
        int gp = i >> 6, r = i & 63, j = r >> 1, e = r & 1;
        g_wbuf[OFF_G2 + i] = g2w[(2 * gp + e) * GH32 + j];
    }
    if (t < 256) {
        int c = t >> 4, d = t & 15;
        g_wbuf[OFF_MW + t] = mw[d * C16 + c] * 0.125f;        // mean factor folded
    }
    if (t < GH32)                g_wbuf[OFF_B1 + t]      = g1b[t];
    if (t >= 32 && t < 32 + C16) g_wbuf[OFF_MB + t - 32] = mb[t - 32];
    if (t >= 64 && t < 64 + C16) g_wbuf[OFF_GB + t - 64] = g2b[t - 64];
}

// ==== K1: gather + agg.  agg = MW' @ (raw 8-neighbor sum) + mb -> g_agg ====
// 32x16 pixel tiles (61 KB halo/block, 27 MB chip-wide: the R11-validated
// geometry), occ-3 is safe because live regs ~50 (sv + streaming agg groups).
__global__ __launch_bounds__(256, 3) void agg_kernel(const float* __restrict__ x)
{
    const int t = threadIdx.x;
    const int b     = blockIdx.x >> 9;
    const int rem   = blockIdx.x & 511;
    const int tileY = rem >> 4;
    const int tileX = rem & 15;
    const int tx = t & 15;
    const int ty = t >> 4;
    const int w0 = tileX * 32 + tx * 2;          // even column
    const int h  = tileY * 16 + ty;

    const float* xb    = x + (size_t)b * C16 * HW;
    const int    center = h * W512 + w0;

    // ---- sv = raw sum of 8 rolls per channel ----
    float2 sv[C16];
    {
        constexpr int DY[8] = {-4, -4, -4, -3, -2, 2, 3, 4};
        constexpr int DX[8] = {-4, -1,  2,  4, -3, 3, -2, 4};
        int roff[8], cb[8];
        #pragma unroll
        for (int i = 0; i < 8; i++) {
            roff[i] = ((h - DY[i]) & (W512 - 1)) * W512;
            cb[i]   = (w0 - DX[i]) & (W512 - 1);
        }
        #pragma unroll
        for (int c = 0; c < C16; c++) {
            const float* xp = xb + c * HW;
            float2 acc = *reinterpret_cast<const float2*>(xp + roff[0] + cb[0]);
            #pragma unroll
            for (int i = 1; i < 8; i++) {
                float2 v;
                if ((DX[i] & 1) == 0) {
                    v = *reinterpret_cast<const float2*>(xp + roff[i] + cb[i]);
                } else {
                    v.x = __ldg(xp + roff[i] + cb[i]);
                    v.y = __ldg(xp + roff[i] + ((cb[i] + 1) & (W512 - 1)));
                }
                acc = fadd2(acc, v);
            }
            sv[c] = acc;
        }
    }

    // ---- agg = MW' @ sv + mb, streamed two d-pairs at a time -> g_agg ----
    float* ab = g_agg + (size_t)b * C16 * HW + center;
    #pragma unroll
    for (int dp = 0; dp < 8; dp += 2) {
        float2 mv0 = ldc2(OFF_MB + 2 * dp);
        float2 mv1 = ldc2(OFF_MB + 2 * dp + 2);
        float2 a00 = mv0, a01 = mv0;
        float2 a10 = mv1, a11 = mv1;
        #pragma unroll
        for (int c = 0; c < C16; c++) {
            float2 sd0 = dup2(sv[c].x), sd1 = dup2(sv[c].y);
            float4 wq = ldc4(OFF_MW + c * C16 + dp * 2);
            a00 = ffma2(make_float2(wq.x, wq.y), sd0, a00);
            a01 = ffma2(make_float2(wq.x, wq.y), sd1, a01);
            a10 = ffma2(make_float2(wq.z, wq.w), sd0, a10);
            a11 = ffma2(make_float2(wq.z, wq.w), sd1, a11);
        }
        #pragma unroll
        for (int e = 0; e < 2; e++) {
            float2 v0 = e ? a10 : a00;
            float2 v1 = e ? a11 : a01;
            const int d0 = 2 * (dp + e);
            *reinterpret_cast<float2*>(ab + (size_t)d0 * HW) =
                make_float2(v0.x, v1.x);
            *reinterpret_cast<float2*>(ab + (size_t)(d0 + 1) * HW) =
                make_float2(v0.y, v1.y);
        }
    }
}

// ==== K2: dense.  hidden = relu(W1@x + WB@agg + g1b);                   ====
// ====            out = agg * sigmoid(G2@hidden + g2b)                   ====
// No gather: both x and agg stream coalesced. Live ~62 regs -> occ-3 spill-
// free and geometry-free. fma floor drops to ~41us (1536 MAC/px).
__global__ __launch_bounds__(256, 3) void dense_kernel(
    const float* __restrict__ x,
    float* __restrict__ out)
{
    const int t = threadIdx.x;
    const int tidg = blockIdx.x * 256 + t;
    const int p0   = tidg * 2;
    const int w0   = p0 & (W512 - 1);
    const int h    = (p0 >> 9) & (W512 - 1);
    const int b    = p0 >> 18;

    const float* xb = x     + (size_t)b * C16 * HW;
    const float* ab = g_agg + (size_t)b * C16 * HW;
    const int center = h * W512 + w0;

    // ---- gate accumulators: gacc[gp][px] packs outputs (2gp, 2gp+1) ----
    float2 gacc[8][2];
    #pragma unroll
    for (int gp = 0; gp < 8; gp++) {
        float2 gb = ldc2(OFF_GB + 2 * gp);
        gacc[gp][0] = gb; gacc[gp][1] = gb;
    }

    // ---- hidden in 4 chunks of 8 units (hreg = 16 regs; occ-3 safe) ----
    #pragma unroll
    for (int jt = 0; jt < 4; jt++) {
        const int j0 = jt * 8;
        float2 hreg[4][2];
        #pragma unroll
        for (int jl = 0; jl < 4; jl++) {
            float2 bv = ldc2(OFF_B1 + j0 + 2 * jl);
            hreg[jl][0] = bv; hreg[jl][1] = bv;
        }
        // W1 @ x  (x center stream, L1/L2-hot across chunks)
        #pragma unroll
        for (int c = 0; c < C16; c++) {
            float2 xc = *reinterpret_cast<const float2*>(xb + c * HW + center);
            float2 xd0 = dup2(xc.x), xd1 = dup2(xc.y);
            float4 wa = ldc4(OFF_W1 + c * GH32 + j0);
            float4 wb = ldc4(OFF_W1 + c * GH32 + j0 + 4);
            hreg[0][0] = ffma2(make_float2(wa.x, wa.y), xd0, hreg[0][0]);
            hreg[0][1] = ffma2(make_float2(wa.x, wa.y), xd1, hreg[0][1]);
            hreg[1][0] = ffma2(make_float2(wa.z, wa.w), xd0, hreg[1][0]);
            hreg[1][1] = ffma2(make_float2(wa.z, wa.w), xd1, hreg[1][1]);
            hreg[2][0] = ffma2(make_float2(wb.x, wb.y), xd0, hreg[2][0]);
            hreg[2][1] = ffma2(make_float2(wb.x, wb.y), xd1, hreg[2][1]);
            hreg[3][0] = ffma2(make_float2(wb.z, wb.w), xd0, hreg[3][0]);
            hreg[3][1] = ffma2(make_float2(wb.z, wb.w), xd1, hreg[3][1]);
        }
        // WB @ agg  (agg stream from K1's scratch)
        #pragma unroll
        for (int k = 0; k < C16; k++) {
            float2 ak = *reinterpret_cast<const float2*>(ab + k * HW + center);
            float2 ad0 = dup2(ak.x), ad1 = dup2(ak.y);
            float4 wa = ldc4(OFF_WB + k * GH32 + j0);
            float4 wb = ldc4(OFF_WB + k * GH32 + j0 + 4);
            hreg[0][0] = ffma2(make_float2(wa.x, wa.y), ad0, hreg[0][0]);
            hreg[0][1] = ffma2(make_float2(wa.x, wa.y), ad1, hreg[0][1]);
            hreg[1][0] = ffma2(make_float2(wa.z, wa.w), ad0, hreg[1][0]);
            hreg[1][1] = ffma2(make_float2(wa.z, wa.w), ad1, hreg[1][1]);
            hreg[2][0] = ffma2(make_float2(wb.x, wb.y), ad0, hreg[2][0]);
            hreg[2][1] = ffma2(make_float2(wb.x, wb.y), ad1, hreg[2][1]);
            hreg[3][0] = ffma2(make_float2(wb.z, wb.w), ad0, hreg[3][0]);
            hreg[3][1] = ffma2(make_float2(wb.z, wb.w), ad1, hreg[3][1]);
        }
        // relu
        #pragma unroll
        for (int jl = 0; jl < 4; jl++) {
            hreg[jl][0].x = fmaxf(hreg[jl][0].x, 0.f);
            hreg[jl][0].y = fmaxf(hreg[jl][0].y, 0.f);
            hreg[jl][1].x = fmaxf(hreg[jl][1].x, 0.f);
            hreg[jl][1].y = fmaxf(hreg[jl][1].y, 0.f);
        }
        // gate accumulation
        #pragma unroll
        for (int jl = 0; jl < 4; jl++) {
            const int jg = j0 + 2 * jl;
            float2 ha0 = dup2(hreg[jl][0].x), hb0 = dup2(hreg[jl][0].y);
            float2 ha1 = dup2(hreg[jl][1].x), hb1 = dup2(hreg[jl][1].y);
            #pragma unroll
            for (int gp = 0; gp < 8; gp++) {
                float4 wq = ldc4(OFF_G2 + gp * 64 + jg * 2);
                gacc[gp][0] = ffma2(make_float2(wq.x, wq.y), ha0, gacc[gp][0]);
                gacc[gp][0] = ffma2(make_float2(wq.z, wq.w), hb0, gacc[gp][0]);
                gacc[gp][1] = ffma2(make_float2(wq.x, wq.y), ha1, gacc[gp][1]);
                gacc[gp][1] = ffma2(make_float2(wq.z, wq.w), hb1, gacc[gp][1]);
            }
        }
    }

    // ---- epilogue: out = agg * sigmoid(gacc); agg re-read (L1/L2-hot) ----
    float* ob = out + (size_t)b * C16 * HW + center;
    #pragma unroll
    for (int q = 0; q < 8; q++) {
        const int d0 = 2 * q;
        float2 a0 = *reinterpret_cast<const float2*>(ab + (size_t)d0 * HW + center);
        float2 a1 = *reinterpret_cast<const float2*>(ab + (size_t)(d0 + 1) * HW + center);
        float g00 = 1.f / (1.f + __expf(-gacc[q][0].x));  // d0   @ px0
        float g01 = 1.f / (1.f + __expf(-gacc[q][1].x));  // d0   @ px1
        float g10 = 1.f / (1.f + __expf(-gacc[q][0].y));  // d0+1 @ px0
        float g11 = 1.f / (1.f + __expf(-gacc[q][1].y));  // d0+1 @ px1
        *reinterpret_cast<float2*>(ob + (size_t)d0 * HW) =
            make_float2(a0.x * g00, a0.y * g01);
        *reinterpret_cast<float2*>(ob + (size_t)(d0 + 1) * HW) =
            make_float2(a1.x * g10, a1.y * g11);
    }
}

extern "C" void kernel_launch(void* const* d_in, const int* in_sizes, int n_in,
                              void* d_out, int out_size) {
    // metadata order: x, qw, qb, kw, kb, mw, mb, scaling, g1w, g1b, g2w, g2b
    const float* x   = (const float*)d_in[0];
    const float* mw  = (const float*)d_in[5];
    const float* mb  = (const float*)d_in[6];
    const float* g1w = (const float*)d_in[8];
    const float* g1b = (const float*)d_in[9];
    const float* g2w = (const float*)d_in[10];
    const float* g2b = (const float*)d_in[11];
    float* out = (float*)d_out;

    prep_weights<<<1, 256>>>(mw, mb, g1w, g1b, g2w, g2b);

    void* wsrc = nullptr;
    cudaGetSymbolAddress(&wsrc, g_wbuf);
    cudaMemcpyToSymbolAsync(cwts, wsrc, NWC * sizeof(float), 0,
                            cudaMemcpyDeviceToDevice, 0);

    // K1: 4 batches x (32 y-tiles x 16 x-tiles) = 2048 blocks, 32x16 px tiles
    agg_kernel<<<2048, 256>>>(x);
    // K2: 524,288 horizontal pairs -> 2048 blocks x 256 threads
    dense_kernel<<<2048, 256>>>(x, out);
}